// round 3
// baseline (speedup 1.0000x reference)
#include <cuda_runtime.h>
#include <cuda_bf16.h>
#include <cstdint>

#define NS   16      // n_samples
#define NP   2048    // n_points
#define DIM  64      // dims
#define KNN  16      // K
#define QT   128     // queries per block (= threads per block)
#define PT   128     // points per shared tile
#define NSPLIT 4     // point-dimension split
#define PPS  (NP / NSPLIT)   // 512 points per split

// partial top-K scratch: [query][split][k], query-major so merge reads 64 contiguous
__device__ float          g_pdist[(size_t)NS * NP * NSPLIT * KNN];   // 8 MB
__device__ unsigned short g_pidx [(size_t)NS * NP * NSPLIT * KNN];   // 4 MB

// ---- packed fp32x2 ops (sm_100+; exactly two scalar fp32 ops) ----
__device__ __forceinline__ uint64_t ffma2(uint64_t a, uint64_t b, uint64_t c) {
    uint64_t d;
    asm("fma.rn.f32x2 %0, %1, %2, %3;" : "=l"(d) : "l"(a), "l"(b), "l"(c));
    return d;
}
__device__ __forceinline__ uint64_t fadd2(uint64_t a, uint64_t b) {
    uint64_t d;
    asm("add.rn.f32x2 %0, %1, %2;" : "=l"(d) : "l"(a), "l"(b));
    return d;
}
__device__ __forceinline__ uint64_t pack2(float lo, float hi) {
    return (uint64_t)__float_as_uint(lo) | ((uint64_t)__float_as_uint(hi) << 32);
}

// ================= phase 1: partial top-K per (query, point-split) ============
__global__ __launch_bounds__(QT, 4)
void knn_partial_kernel(const float* __restrict__ h)
{
    __shared__ __align__(16) float pts[PT][DIM];   // 32 KB point tile
    __shared__ float pnorm[PT];

    const int s   = blockIdx.x / (NP / QT);
    const int qt  = blockIdx.x % (NP / QT);
    const int ps  = blockIdx.y;              // point split 0..3
    const int tid = threadIdx.x;
    const int qi  = qt * QT + tid;

    const float* hs = h + (size_t)s * NP * DIM;

    // ---- query row into packed f32x2 registers + norm ----
    uint64_t qq[DIM / 2];
    float    qn = 0.0f;
    {
        const float4* qp = reinterpret_cast<const float4*>(hs + (size_t)qi * DIM);
        #pragma unroll
        for (int i = 0; i < DIM / 4; i++) {
            float4 v = qp[i];
            qn += v.x * v.x + v.y * v.y + v.z * v.z + v.w * v.w;
            qq[2 * i]     = pack2(v.x, v.y);
            qq[2 * i + 1] = pack2(v.z, v.w);
        }
    }

    // ---- per-thread top-K (sorted ascending; ties keep earlier index) ----
    float          best_d[KNN];
    unsigned short best_i[KNN];
    #pragma unroll
    for (int k = 0; k < KNN; k++) { best_d[k] = 3.4e38f; best_i[k] = 0; }

    const int j0 = ps * PPS;
    for (int jt = j0; jt < j0 + PPS; jt += PT) {
        __syncthreads();
        {   // cooperative coalesced tile load
            const float4* tp = reinterpret_cast<const float4*>(hs + (size_t)jt * DIM);
            float4*       sp = reinterpret_cast<float4*>(&pts[0][0]);
            #pragma unroll
            for (int i = 0; i < (PT * DIM / 4) / QT; i++)
                sp[tid + i * QT] = tp[tid + i * QT];
        }
        __syncthreads();
        {   // point norms (thread t -> point t)
            float pn = 0.0f;
            #pragma unroll
            for (int i = 0; i < DIM / 4; i++) {
                float4 v = reinterpret_cast<const float4*>(&pts[tid][0])[i];
                pn += v.x * v.x + v.y * v.y + v.z * v.z + v.w * v.w;
            }
            pnorm[tid] = pn;
        }
        __syncthreads();

        #pragma unroll 2
        for (int jj = 0; jj < PT; jj++) {
            const ulonglong2* pp = reinterpret_cast<const ulonglong2*>(&pts[jj][0]);
            uint64_t a0 = 0, a1 = 0, a2 = 0, a3 = 0;
            #pragma unroll
            for (int i = 0; i < DIM / 4; i += 2) {     // 16 x LDS.128
                ulonglong2 v0 = pp[i];
                ulonglong2 v1 = pp[i + 1];
                a0 = ffma2(qq[2 * i],     v0.x, a0);
                a1 = ffma2(qq[2 * i + 1], v0.y, a1);
                a2 = ffma2(qq[2 * i + 2], v1.x, a2);
                a3 = ffma2(qq[2 * i + 3], v1.y, a3);
            }
            uint64_t sred = fadd2(fadd2(a0, a1), fadd2(a2, a3));
            float lo  = __uint_as_float((uint32_t)sred);
            float hi  = __uint_as_float((uint32_t)(sred >> 32));
            float dist = fmaf(-2.0f, lo + hi, qn + pnorm[jj]);

            // strict <: tie with current worst keeps earlier index
            if (dist < best_d[KNN - 1]) {
                float dd  = dist;
                unsigned short idx = (unsigned short)(jt + jj);
                #pragma unroll
                for (int k = 0; k < KNN; k++) {
                    if (dd < best_d[k]) {
                        float td = best_d[k]; unsigned short ti = best_i[k];
                        best_d[k] = dd;  best_i[k] = idx;
                        dd = td;         idx = ti;
                    }
                }
            }
        }
    }

    // ---- write partial sorted list ----
    const size_t pbase = (((size_t)s * NP + qi) * NSPLIT + ps) * KNN;
    #pragma unroll
    for (int k = 0; k < KNN; k++) {
        g_pdist[pbase + k] = best_d[k];
        g_pidx [pbase + k] = best_i[k];
    }
}

// ================= phase 2: 4-way merge of sorted partial lists ===============
__global__ __launch_bounds__(QT, 4)
void knn_merge_kernel(float* __restrict__ out_dist,
                      float* __restrict__ out_dst,
                      float* __restrict__ out_src)
{
    __shared__ float sdist[QT][NSPLIT * KNN + 1];   // +1 pad: 33.3 KB

    const int tid = threadIdx.x;
    const int qg  = blockIdx.x * QT + tid;          // global query id 0..32767
    const int s   = qg / NP;

    // stage this block's 128 queries x 64 partial dists, coalesced
    {
        const float* src = g_pdist + (size_t)blockIdx.x * QT * (NSPLIT * KNN);
        for (int i = tid; i < QT * NSPLIT * KNN; i += QT) {
            int r = i / (NSPLIT * KNN);
            int c = i % (NSPLIT * KNN);
            sdist[r][c] = src[i];
        }
    }
    __syncthreads();

    const size_t pbase = (size_t)qg * (NSPLIT * KNN);
    const size_t obase = (size_t)qg * KNN;
    const float  srcv  = (float)qg;                 // qg already includes s*NP
    const float  offs  = (float)(s * NP);

    int c0 = 0, c1 = 0, c2 = 0, c3 = 0;
    for (int k = 0; k < KNN; k++) {
        float bv = 3.5e38f; int bl = 0, bc = 0;
        // scan lists in index order; strict < keeps earlier (lower-index) list on ties
        if (c0 < KNN) { float v = sdist[tid][ 0 + c0]; if (v < bv) { bv = v; bl = 0; bc = c0; } }
        if (c1 < KNN) { float v = sdist[tid][16 + c1]; if (v < bv) { bv = v; bl = 1; bc = c1; } }
        if (c2 < KNN) { float v = sdist[tid][32 + c2]; if (v < bv) { bv = v; bl = 2; bc = c2; } }
        if (c3 < KNN) { float v = sdist[tid][48 + c3]; if (v < bv) { bv = v; bl = 3; bc = c3; } }

        int gidx = (int)g_pidx[pbase + bl * KNN + bc] ;
        c0 += (bl == 0); c1 += (bl == 1); c2 += (bl == 2); c3 += (bl == 3);

        out_dist[obase + k] = bv;
        out_dst [obase + k] = (float)gidx + offs;
        out_src [obase + k] = srcv;
    }
}

extern "C" void kernel_launch(void* const* d_in, const int* in_sizes, int n_in,
                              void* d_out, int out_size)
{
    const float* h = (const float*)d_in[0];

    float* out      = (float*)d_out;
    const size_t nE = (size_t)NS * NP * KNN;   // 524288
    float* out_dist = out;
    float* out_dst  = out + nE;
    float* out_src  = out + 2 * nE;

    dim3 grid1(NS * (NP / QT), NSPLIT);   // 256 x 4 = 1024 blocks
    knn_partial_kernel<<<grid1, QT>>>(h);

    dim3 grid2(NS * NP / QT);             // 256 blocks
    knn_merge_kernel<<<grid2, QT>>>(out_dist, out_dst, out_src);
}